// round 13
// baseline (speedup 1.0000x reference)
#include <cuda_runtime.h>
#include <cuda_bf16.h>
#include <cstdint>

#define DIM      4096
#define THREADS  64
#define NCTA     888        // 148 SMs * 6 resident CTAs (2x16KB smem + reserved = 33KB)

__device__ unsigned g_row_ctr;   // work-stealing row counter (memset to 0 each launch)

__device__ __forceinline__ void fwht64(float v[64]) {
#pragma unroll
    for (int h = 1; h < 64; h <<= 1) {
#pragma unroll
        for (int i = 0; i < 64; i++) {
            if ((i & h) == 0) {
                float a = v[i];
                float b = v[i | h];
                v[i]     = a + b;
                v[i | h] = a - b;
            }
        }
    }
}

// Physical smem layout: word phys(i) = i ^ (((i>>6)&7)<<2)  (toggles word bits 2-4).
// - r1 float4 reads  (thread t, i = t*64+k):  chunk pos = (kg^(t&7)) -> balanced, 4 wf/instr (optimal)
// - r1 scalar writes (same addresses):        banks = lane low bits  -> conflict-free
// - r2 scalar reads  (i = r*64+u):            banks = u0..u4         -> conflict-free
// 16B-granule map: g' = g ^ ((g>>4)&7)  -> cp.async stages gmem-coalesced directly into this layout.

__device__ __forceinline__ void stage_row(uint32_t dst_base, const float* __restrict__ src_row,
                                          int t) {
    const float4* __restrict__ src = reinterpret_cast<const float4*>(src_row);
    const int pe = t >> 4;                 // (t>>4)&3, t < 64
    const int te = t ^ pe;                 // even j: pg = t>>4
    const int to = t ^ (pe | 4);           // odd  j: pg = 4 | (t>>4)
#pragma unroll
    for (int j = 0; j < 16; j++) {
        const int tt = (j & 1) ? to : te;
        uint32_t dst = dst_base + (uint32_t)((j * 64 + tt) * 16);
        asm volatile("cp.async.cg.shared.global [%0], [%1], 16;\n"
                     :: "r"(dst), "l"(src + j * 64 + t));
    }
    asm volatile("cp.async.commit_group;\n" ::: "memory");
}

__global__ __launch_bounds__(THREADS, 6)
void fwht4096_kernel(const float* __restrict__ x, float* __restrict__ y, int nrows) {
    __shared__ float s[2][DIM];
    __shared__ int s_nxt;

    const int t = threadIdx.x;             // 0..63
    const int q = t & 7;

    const uint32_t sb0 = (uint32_t)__cvta_generic_to_shared(&s[0][0]);
    const uint32_t sb1 = (uint32_t)__cvta_generic_to_shared(&s[1][0]);

    // r2 address helpers: phys = r*64 + (u ^ ((r&7)<<2));  u = t here.
    int ux[8];
#pragma unroll
    for (int p = 0; p < 8; p++) ux[p] = t ^ (p << 2);

    // Prologue: pop first row, stage into buffer 0.
    if (t == 0) s_nxt = (int)atomicAdd(&g_row_ctr, 1u);
    __syncthreads();
    int r_cur = s_nxt;
    if (r_cur >= nrows) return;            // uniform across CTA
    stage_row(sb0, x + (size_t)r_cur * DIM, t);

    int buf = 0;
    while (true) {
        asm volatile("cp.async.wait_group 0;\n" ::: "memory");
        __syncthreads();                   // BAR1: all staging of current row visible

        // Pop next row AFTER BAR1 (prev readers passed), read after BAR2 -> race-free.
        if (t == 0) s_nxt = (int)atomicAdd(&g_row_ctr, 1u);

        float* sb = buf ? s[1] : s[0];
        float v[64];

        // ---- Round 1: bits b0..b5 (thread owns i = t*64 + k, k = 0..63) ----
        {
            const float4* sf4 = reinterpret_cast<const float4*>(sb) + t * 16;
#pragma unroll
            for (int kg = 0; kg < 16; kg++) {
                float4 f = sf4[kg ^ q];
                v[kg * 4 + 0] = f.x;
                v[kg * 4 + 1] = f.y;
                v[kg * 4 + 2] = f.z;
                v[kg * 4 + 3] = f.w;
            }
            fwht64(v);
            float* sbw = sb + t * 64;
            const int q4 = q << 2;
#pragma unroll
            for (int k = 0; k < 64; k++)
                sbw[k ^ q4] = v[k];        // same addresses as read -> no intra-phase sync
        }
        __syncthreads();                   // BAR2: round-1 results visible; s_nxt visible

        // Prefetch next row into the other buffer (free since BAR1).
        const int r_next = s_nxt;
        if (r_next < nrows)
            stage_row(buf ? sb0 : sb1, x + (size_t)r_next * DIM, t);

        // ---- Round 2: bits b6..b11 (thread owns i = r*64 + t, r = 0..63) ----
#pragma unroll
        for (int r = 0; r < 64; r++)
            v[r] = sb[r * 64 + ux[r & 7]];
        fwht64(v);

        // Store: per instr lanes cover t -> 128B coalesced. Scale 1/sqrt(4096) = 1/64.
        float* yr = y + (size_t)r_cur * DIM + t;
#pragma unroll
        for (int r = 0; r < 64; r++)
            __stcs(yr + r * 64, v[r] * 0.015625f);

        if (r_next >= nrows) break;
        r_cur = r_next;
        buf ^= 1;
    }
}

extern "C" void kernel_launch(void* const* d_in, const int* in_sizes, int n_in,
                              void* d_out, int out_size) {
    const float* x = (const float*)d_in[0];
    float* y = (float*)d_out;
    int rows = in_sizes[0] / DIM;          // 8192

    void* ctr = nullptr;
    cudaGetSymbolAddress(&ctr, g_row_ctr);
    cudaMemsetAsync(ctr, 0, sizeof(unsigned));   // capturable, allocation-free

    int grid = NCTA < rows ? NCTA : rows;
    fwht4096_kernel<<<grid, THREADS>>>(x, y, rows);
}

// round 16
// speedup vs baseline: 1.0433x; 1.0433x over previous
#include <cuda_runtime.h>
#include <cuda_bf16.h>
#include <cstdint>

#define DIM      4096
#define THREADS  256
#define NCTA     888        // 148 SMs * 6 resident CTAs (33KB smem/CTA incl. reserved)

__device__ unsigned g_row_ctr;    // work-stealing row counter (self-resetting)
__device__ unsigned g_done_ctr;   // CTA exit counter (self-resetting)

__device__ __forceinline__ void fwht16(float v[16]) {
#pragma unroll
    for (int h = 1; h < 16; h <<= 1) {
#pragma unroll
        for (int i = 0; i < 16; i++) {
            if ((i & h) == 0) {
                float a = v[i];
                float b = v[i | h];
                v[i]     = a + b;
                v[i | h] = a - b;
            }
        }
    }
}

// Physical smem layout: word phys(i) = i ^ (((i>>6)&7)<<2)  (toggles word bits 2-4).
// Bank bits (b0, b1, b2^b6, b3^b7, b4^b8) are injective on each phase's
// lane-varying bits -> all patterns conflict-free; bits 0-1 identity -> 128-bit
// smem ops legal in phase A. 16B-granule map: g' = g ^ ((g>>4)&7), so cp.async
// stages directly into the swizzled layout and each thread stages exactly the
// granules it alone reads in phase A (self-dependency -> no barrier after stage).

__device__ __forceinline__ void stage_row(uint32_t dst_base, const float* __restrict__ src_row,
                                          int t, int pg) {
#pragma unroll
    for (int g = 0; g < 4; g++) {
        uint32_t dst = dst_base + (uint32_t)(((g * 256 + t) ^ pg) * 16);
        const float4* src = reinterpret_cast<const float4*>(src_row) + (g * 256 + t);
        asm volatile("cp.async.cg.shared.global [%0], [%1], 16;\n"
                     :: "r"(dst), "l"(src));
    }
    asm volatile("cp.async.commit_group;\n" ::: "memory");
}

__device__ __forceinline__ void cta_retire(int t) {
    // Last CTA out resets both counters -> next launch/replay starts from zero
    // with NO host-side memset node in the graph.
    if (t == 0) {
        __threadfence();
        unsigned done = atomicAdd(&g_done_ctr, 1u);
        if (done == (unsigned)(gridDim.x - 1)) {
            atomicExch(&g_row_ctr, 0u);
            atomicExch(&g_done_ctr, 0u);
        }
    }
}

__global__ __launch_bounds__(THREADS, 6)
void fwht4096_kernel(const float* __restrict__ x, float* __restrict__ y, int nrows) {
    __shared__ float s[2][DIM];
    __shared__ int s_nxt;

    const int t  = threadIdx.x;
    const int pg = (t >> 4) & 7;
    const int e  = t & 3;
    const int m  = (t >> 2) & 15;
    const int d  = t >> 6;
    const int mq = (m & 7) << 2;
    const int baseB = d * 1024 + m * 64 + e;   // word bits 2-5 zero
    const int baseC = d * 1024 + 4 * m + e;    // word bits 6-9 zero

    const uint32_t sb0 = (uint32_t)__cvta_generic_to_shared(&s[0][0]);
    const uint32_t sb1 = (uint32_t)__cvta_generic_to_shared(&s[1][0]);

    // Prologue: pop first row, stage it.
    if (t == 0) s_nxt = (int)atomicAdd(&g_row_ctr, 1u);
    __syncthreads();
    int r_cur = s_nxt;
    if (r_cur >= nrows) { cta_retire(t); return; }   // uniform across CTA
    stage_row(sb0, x + (size_t)r_cur * DIM, t, pg);

    int buf = 0;
    while (true) {
        asm volatile("cp.async.wait_group 0;\n" ::: "memory");
        float* sb = buf ? s[1] : s[0];
        float v[16];

        // ---- Phase A: bits {b0,b1,b10,b11} (reads own staged granules) ----
#pragma unroll
        for (int g = 0; g < 4; g++) {
            float4 f = *reinterpret_cast<const float4*>(&sb[(size_t)((g * 256 + t) ^ pg) * 4]);
            v[4 * g + 0] = f.x;
            v[4 * g + 1] = f.y;
            v[4 * g + 2] = f.z;
            v[4 * g + 3] = f.w;
        }
        fwht16(v);
#pragma unroll
        for (int g = 0; g < 4; g++) {
            float4 f = make_float4(v[4 * g + 0], v[4 * g + 1], v[4 * g + 2], v[4 * g + 3]);
            *reinterpret_cast<float4*>(&sb[(size_t)((g * 256 + t) ^ pg) * 4]) = f;
        }
        __syncthreads();   // B1: A-write visible; also proves all threads finished prev iter

        // Pop next row (written after B1, read after B2 -> race-free vs prior read)
        if (t == 0) s_nxt = (int)atomicAdd(&g_row_ctr, 1u);

        // ---- Phase B: bits {b2..b5};  phys = baseB + (4k ^ mq) ----
#pragma unroll
        for (int k = 0; k < 16; k++)
            v[k] = sb[baseB + ((4 * k) ^ mq)];
        fwht16(v);
#pragma unroll
        for (int k = 0; k < 16; k++)
            sb[baseB + ((4 * k) ^ mq)] = v[k];   // same addresses -> no sync needed
        __syncthreads();   // B2: B-write visible; s_nxt visible

        // Prefetch next row into the other buffer. Safe: all threads passed B1,
        // so everyone finished reading that buffer in the previous iteration.
        const int r_next = s_nxt;
        if (r_next < nrows)
            stage_row(buf ? sb0 : sb1, x + (size_t)r_next * DIM, t, pg);

        // ---- Phase C: bits {b6..b9};  phys = (baseC ^ ((k&7)<<2)) + 64k ----
#pragma unroll
        for (int k = 0; k < 16; k++)
            v[k] = sb[(baseC ^ ((k & 7) << 2)) + 64 * k];
        fwht16(v);

        float* yr = y + (size_t)r_cur * DIM;
#pragma unroll
        for (int k = 0; k < 16; k++)
            __stcs(yr + baseC + 64 * k, v[k] * 0.015625f);   // 1/sqrt(4096)

        if (r_next >= nrows) break;
        r_cur = r_next;
        buf ^= 1;
    }

    cta_retire(t);
}

extern "C" void kernel_launch(void* const* d_in, const int* in_sizes, int n_in,
                              void* d_out, int out_size) {
    const float* x = (const float*)d_in[0];
    float* y = (float*)d_out;
    int rows = in_sizes[0] / DIM;          // 8192
    int grid = NCTA < rows ? NCTA : rows;
    fwht4096_kernel<<<grid, THREADS>>>(x, y, rows);   // single graph node, no memset
}